// round 1
// baseline (speedup 1.0000x reference)
#include <cuda_runtime.h>
#include <math.h>

#define Bn 2
#define Cn 64
#define Hn 192
#define Wn 192
#define HWn (Hn*Wn)
#define Gn 4
#define CGn 16
#define Kn 9

// Scratch (no allocations allowed): NHWC copy of warp_ref + modulator
__device__ float g_xnhwc[Bn*HWn*Cn];
__device__ float g_mod[Bn*Gn*Kn*HWn];

// ---------------------------------------------------------------------------
// NCHW -> NHWC transpose of warp_ref (for vectorized bilinear gathers)
// ---------------------------------------------------------------------------
__global__ void k_transpose(const float* __restrict__ x) {
    __shared__ float t[32][33];
    int b   = blockIdx.z;
    int hw0 = blockIdx.x * 32;
    int c0  = blockIdx.y * 32;
    #pragma unroll
    for (int i = 0; i < 4; i++) {
        int c = c0 + threadIdx.y + i*8;
        t[threadIdx.y + i*8][threadIdx.x] = x[(b*Cn + c)*HWn + hw0 + threadIdx.x];
    }
    __syncthreads();
    #pragma unroll
    for (int i = 0; i < 4; i++) {
        int hw = hw0 + threadIdx.y + i*8;
        g_xnhwc[(size_t)(b*HWn + hw)*Cn + c0 + threadIdx.x] = t[threadIdx.x][threadIdx.y + i*8];
    }
}

// ---------------------------------------------------------------------------
// Offset conv: per group g, conv([wr_g(16) ; src_g(16)]) with offset_w[18,32,3,3]
// + bias, then 100*sigmoid - 50 = 50*tanh(z/2). Written into d_out offset slice.
// Block: 16x16 pixel tile (256 thr), one thread computes all 18 out channels.
// ---------------------------------------------------------------------------
__global__ void k_offset(const float* __restrict__ wr, const float* __restrict__ src,
                         const float* __restrict__ ow, const float* __restrict__ ob,
                         float* __restrict__ offout) {
    __shared__ float sW[18*32*9];   // full offset weights (shared across groups)
    __shared__ float sT[16*18*18];  // 16-channel input tile with halo
    int tid = threadIdx.x;
    int g = blockIdx.y, b = blockIdx.z;
    int th = (blockIdx.x / 12) * 16, tw = (blockIdx.x % 12) * 16;
    for (int i = tid; i < 18*32*9; i += 256) sW[i] = ow[i];

    float acc[18];
    #pragma unroll
    for (int o = 0; o < 18; o++) acc[o] = 0.f;

    int lyy = tid >> 4, lxx = tid & 15;

    for (int half = 0; half < 2; half++) {
        const float* base = (half == 0 ? wr : src) + (size_t)(b*Cn + g*CGn)*HWn;
        __syncthreads();
        for (int i = tid; i < 16*18*18; i += 256) {
            int c = i / 324; int r = (i % 324) / 18; int cc = i % 18;
            int y = th + r - 1, x = tw + cc - 1;
            float v = 0.f;
            if ((unsigned)y < (unsigned)Hn && (unsigned)x < (unsigned)Wn)
                v = base[c*HWn + y*Wn + x];
            sT[i] = v;
        }
        __syncthreads();
        for (int c = 0; c < 16; c++) {
            #pragma unroll
            for (int kh = 0; kh < 3; kh++) {
                #pragma unroll
                for (int kw = 0; kw < 3; kw++) {
                    float xv = sT[c*324 + (lyy+kh)*18 + lxx + kw];
                    int widx = (half*16 + c)*9 + kh*3 + kw;
                    #pragma unroll
                    for (int o = 0; o < 18; o++)
                        acc[o] = fmaf(xv, sW[o*288 + widx], acc[o]);
                }
            }
        }
    }
    int h = th + lyy, w = tw + lxx;
    #pragma unroll
    for (int o = 0; o < 18; o++) {
        float z = acc[o] + ob[o];
        offout[(size_t)(b*72 + g*18 + o)*HWn + h*Wn + w] = 50.f * tanhf(0.5f * z);
    }
}

// ---------------------------------------------------------------------------
// Modulator conv: conv(warp_ref, mod_w[36,64,3,3]) + bias, 2*sigmoid = 1+tanh(z/2).
// blockIdx.y selects 18-output-channel half; 4 input-channel chunks of 16.
// ---------------------------------------------------------------------------
__global__ void k_mod(const float* __restrict__ wr, const float* __restrict__ mw,
                      const float* __restrict__ mb) {
    __shared__ float sW[18*16*9];
    __shared__ float sT[16*18*18];
    int tid = threadIdx.x;
    int obase = blockIdx.y * 18;
    int b = blockIdx.z;
    int th = (blockIdx.x / 12) * 16, tw = (blockIdx.x % 12) * 16;

    float acc[18];
    #pragma unroll
    for (int o = 0; o < 18; o++) acc[o] = 0.f;

    int lyy = tid >> 4, lxx = tid & 15;

    for (int chunk = 0; chunk < 4; chunk++) {
        __syncthreads();
        for (int i = tid; i < 18*16*9; i += 256) {
            int o = i / 144; int c = (i % 144) / 9; int k = i % 9;
            sW[i] = mw[(size_t)((obase + o)*Cn + chunk*16 + c)*9 + k];
        }
        const float* base = wr + (size_t)(b*Cn + chunk*16)*HWn;
        for (int i = tid; i < 16*18*18; i += 256) {
            int c = i / 324; int r = (i % 324) / 18; int cc = i % 18;
            int y = th + r - 1, x = tw + cc - 1;
            float v = 0.f;
            if ((unsigned)y < (unsigned)Hn && (unsigned)x < (unsigned)Wn)
                v = base[c*HWn + y*Wn + x];
            sT[i] = v;
        }
        __syncthreads();
        for (int c = 0; c < 16; c++) {
            #pragma unroll
            for (int kh = 0; kh < 3; kh++) {
                #pragma unroll
                for (int kw = 0; kw < 3; kw++) {
                    float xv = sT[c*324 + (lyy+kh)*18 + lxx + kw];
                    int widx = c*9 + kh*3 + kw;
                    #pragma unroll
                    for (int o = 0; o < 18; o++)
                        acc[o] = fmaf(xv, sW[o*144 + widx], acc[o]);
                }
            }
        }
    }
    int h = th + lyy, w = tw + lxx;
    #pragma unroll
    for (int o = 0; o < 18; o++) {
        float z = acc[o] + mb[obase + o];
        g_mod[(size_t)(b*36 + obase + o)*HWn + h*Wn + w] = 1.f + tanhf(0.5f * z);
    }
}

// ---------------------------------------------------------------------------
// Deformable conv: 1 thread per output pixel, 64 fp32 accumulators.
// Per group: stage reg_w slice in smem as [k][c][co] (co contiguous -> LDS.128).
// Bilinear corners fetch 16 contiguous channels (NHWC) as 4x float4.
// ---------------------------------------------------------------------------
__global__ void __launch_bounds__(128, 4)
k_deform(const float* __restrict__ rw, const float* __restrict__ offmap,
         float* __restrict__ out) {
    __shared__ float sW[Kn*CGn*Cn];  // 9216 floats = 36 KB
    int tid = threadIdx.x;
    int p  = blockIdx.x * 128 + tid;
    int b  = p / HWn;
    int hw = p - b*HWn;
    int h  = hw / Wn, w = hw - h*Wn;

    float4 acc[16];
    #pragma unroll
    for (int j = 0; j < 16; j++) acc[j] = make_float4(0.f,0.f,0.f,0.f);

    for (int g = 0; g < Gn; g++) {
        __syncthreads();
        for (int i = tid; i < Kn*CGn*Cn; i += 128) {
            int k = i >> 10; int c = (i >> 6) & 15; int co = i & 63;
            sW[i] = rw[(size_t)(co*Cn + g*CGn + c)*Kn + k];
        }
        __syncthreads();

        const float* offb = offmap + (size_t)(b*72 + g*18)*HWn + hw;
        const float* modb = g_mod  + (size_t)(b*36 + g*9 )*HWn + hw;
        const float* xb   = g_xnhwc + (size_t)b*HWn*Cn + g*CGn;

        #pragma unroll 1
        for (int k = 0; k < 9; k++) {
            float oy = offb[(2*k  )*HWn];
            float ox = offb[(2*k+1)*HWn];
            float m  = modb[k*HWn];
            float yf = oy + (float)(k/3 + h - 1);
            float xf = ox + (float)(k%3 + w - 1);
            float y0f = floorf(yf), x0f = floorf(xf);
            int   y0  = (int)y0f,   x0  = (int)x0f;
            float ly = yf - y0f, lx = xf - x0f;
            float w00 = (1.f-ly)*(1.f-lx)*m;
            float w01 = (1.f-ly)*lx*m;
            float w10 = ly*(1.f-lx)*m;
            float w11 = ly*lx*m;

            float4 v[4];
            #pragma unroll
            for (int j = 0; j < 4; j++) v[j] = make_float4(0.f,0.f,0.f,0.f);

            #pragma unroll
            for (int corner = 0; corner < 4; corner++) {
                int yi = y0 + (corner >> 1);
                int xi = x0 + (corner & 1);
                float wc = (corner == 0) ? w00 : (corner == 1) ? w01 :
                           (corner == 2) ? w10 : w11;
                if ((unsigned)yi < (unsigned)Hn && (unsigned)xi < (unsigned)Wn) {
                    const float4* pp = (const float4*)(xb + (size_t)(yi*Wn + xi)*Cn);
                    #pragma unroll
                    for (int j = 0; j < 4; j++) {
                        float4 xv = pp[j];
                        v[j].x = fmaf(wc, xv.x, v[j].x);
                        v[j].y = fmaf(wc, xv.y, v[j].y);
                        v[j].z = fmaf(wc, xv.z, v[j].z);
                        v[j].w = fmaf(wc, xv.w, v[j].w);
                    }
                }
            }

            const float* vf = (const float*)v;
            const float* wk = sW + (k << 10);
            #pragma unroll
            for (int c = 0; c < 16; c++) {
                float vc = vf[c];
                const float4* wp = (const float4*)(wk + (c << 6));
                #pragma unroll
                for (int j = 0; j < 16; j++) {
                    float4 wv = wp[j];
                    acc[j].x = fmaf(vc, wv.x, acc[j].x);
                    acc[j].y = fmaf(vc, wv.y, acc[j].y);
                    acc[j].z = fmaf(vc, wv.z, acc[j].z);
                    acc[j].w = fmaf(vc, wv.w, acc[j].w);
                }
            }
        }
    }

    float* obp = out + (size_t)b*Cn*HWn + hw;
    #pragma unroll
    for (int j = 0; j < 16; j++) {
        obp[(4*j+0)*HWn] = acc[j].x;
        obp[(4*j+1)*HWn] = acc[j].y;
        obp[(4*j+2)*HWn] = acc[j].z;
        obp[(4*j+3)*HWn] = acc[j].w;
    }
}

// ---------------------------------------------------------------------------
extern "C" void kernel_launch(void* const* d_in, const int* in_sizes, int n_in,
                              void* d_out, int out_size) {
    const float* wr  = (const float*)d_in[0];  // warp_ref [2,64,192,192]
    const float* src = (const float*)d_in[1];  // source   [2,64,192,192]
    const float* ow  = (const float*)d_in[2];  // offset_w [18,32,3,3]
    const float* obv = (const float*)d_in[3];  // offset_b [18]
    const float* mw  = (const float*)d_in[4];  // mod_w    [36,64,3,3]
    const float* mbv = (const float*)d_in[5];  // mod_b    [36]
    const float* rw  = (const float*)d_in[6];  // reg_w    [64,64,3,3]

    float* out    = (float*)d_out;             // x: [2,64,192,192]
    float* offout = out + (size_t)Bn*Cn*HWn;   // offset_map: [2,72,192,192]

    k_transpose<<<dim3(HWn/32, 2, Bn), dim3(32, 8)>>>(wr);
    k_offset  <<<dim3(144, Gn, Bn), 256>>>(wr, src, ow, obv, offout);
    k_mod     <<<dim3(144, 2, Bn), 256>>>(wr, mw, mbv);
    k_deform  <<<(Bn*HWn)/128, 128>>>(rw, offout, out);
}

// round 3
// speedup vs baseline: 1.3511x; 1.3511x over previous
#include <cuda_runtime.h>
#include <math.h>

#define Bn 2
#define Cn 64
#define Hn 192
#define Wn 192
#define HWn (Hn*Wn)
#define Gn 4
#define CGn 16
#define Kn 9

// Scratch: NHWC copy of warp_ref + modulator
__device__ float g_xnhwc[Bn*HWn*Cn];
__device__ float g_mod[Bn*Gn*Kn*HWn];

// ---------------------------------------------------------------------------
// NCHW -> NHWC transpose of warp_ref
// ---------------------------------------------------------------------------
__global__ void k_transpose(const float* __restrict__ x) {
    __shared__ float t[32][33];
    int b   = blockIdx.z;
    int hw0 = blockIdx.x * 32;
    int c0  = blockIdx.y * 32;
    #pragma unroll
    for (int i = 0; i < 4; i++) {
        int c = c0 + threadIdx.y + i*8;
        t[threadIdx.y + i*8][threadIdx.x] = x[(b*Cn + c)*HWn + hw0 + threadIdx.x];
    }
    __syncthreads();
    #pragma unroll
    for (int i = 0; i < 4; i++) {
        int hw = hw0 + threadIdx.y + i*8;
        g_xnhwc[(size_t)(b*HWn + hw)*Cn + c0 + threadIdx.x] = t[threadIdx.x][threadIdx.y + i*8];
    }
}

// ---------------------------------------------------------------------------
// Offset conv. Tile 16x32 output pixels per block (256 thr, 2 px/thread in x).
// Weights in smem as [c][kidx][o(pad20)] -> LDS.128, each feeding 40 FFMA.
// 4 chunks of 8 input channels: chunks 0-1 from warp_ref, 2-3 from source.
// ---------------------------------------------------------------------------
__global__ void k_offset(const float* __restrict__ wr, const float* __restrict__ src,
                         const float* __restrict__ ow, const float* __restrict__ ob,
                         float* __restrict__ offout) {
    __shared__ float sT[8*18*35];   // 5040 floats (rows padded to 35, odd)
    __shared__ float sWp[8*9*20];   // 1440 floats
    int tid = threadIdx.x;
    int g = blockIdx.y, b = blockIdx.z;
    int th = (blockIdx.x / 6) * 16, tw = (blockIdx.x % 6) * 32;
    int lyy = tid >> 4, lxx = tid & 15;

    float4 acc0[5], acc1[5];
    #pragma unroll
    for (int j = 0; j < 5; j++) { acc0[j] = make_float4(0,0,0,0); acc1[j] = make_float4(0,0,0,0); }

    for (int chunk = 0; chunk < 4; chunk++) {
        const float* base = (chunk < 2 ? wr : src) + (size_t)(b*Cn + g*CGn + (chunk&1)*8)*HWn;
        __syncthreads();
        for (int i = tid; i < 1440; i += 256) {
            int c = i / 180; int r = i % 180; int widx = r / 20; int o = r % 20;
            float v = 0.f;
            if (o < 18) v = ow[(size_t)(o*32 + chunk*8 + c)*9 + widx];
            sWp[i] = v;
        }
        for (int i = tid; i < 8*18*35; i += 256) {
            int c = i / 630; int r2 = i % 630; int rr = r2 / 35; int cc = r2 % 35;
            int y = th + rr - 1, x = tw + cc - 1;
            float v = 0.f;
            if (cc < 34 && (unsigned)y < (unsigned)Hn && (unsigned)x < (unsigned)Wn)
                v = base[c*HWn + y*Wn + x];
            sT[i] = v;
        }
        __syncthreads();
        for (int c = 0; c < 8; c++) {
            #pragma unroll
            for (int kh = 0; kh < 3; kh++) {
                const float* rowp = sT + c*630 + (lyy+kh)*35 + 2*lxx;
                float xv[4];
                xv[0] = rowp[0]; xv[1] = rowp[1]; xv[2] = rowp[2]; xv[3] = rowp[3];
                #pragma unroll
                for (int kw = 0; kw < 3; kw++) {
                    const float4* wp = (const float4*)(sWp + (c*9 + kh*3 + kw)*20);
                    float a0 = xv[kw], a1 = xv[kw+1];
                    #pragma unroll
                    for (int j = 0; j < 5; j++) {
                        float4 wv = wp[j];
                        acc0[j].x = fmaf(a0, wv.x, acc0[j].x); acc1[j].x = fmaf(a1, wv.x, acc1[j].x);
                        acc0[j].y = fmaf(a0, wv.y, acc0[j].y); acc1[j].y = fmaf(a1, wv.y, acc1[j].y);
                        acc0[j].z = fmaf(a0, wv.z, acc0[j].z); acc1[j].z = fmaf(a1, wv.z, acc1[j].z);
                        acc0[j].w = fmaf(a0, wv.w, acc0[j].w); acc1[j].w = fmaf(a1, wv.w, acc1[j].w);
                    }
                }
            }
        }
    }
    int h = th + lyy, w = tw + 2*lxx;
    const float* a0 = (const float*)acc0;
    const float* a1 = (const float*)acc1;
    #pragma unroll
    for (int o = 0; o < 18; o++) {
        float bo = ob[o];
        float2 r;
        r.x = 50.f * tanhf(0.5f * (a0[o] + bo));
        r.y = 50.f * tanhf(0.5f * (a1[o] + bo));
        *(float2*)(offout + (size_t)(b*72 + g*18 + o)*HWn + h*Wn + w) = r;
    }
}

// ---------------------------------------------------------------------------
// Modulator conv: same structure, 8 chunks of 8 over 64 input channels,
// blockIdx.y selects 18-output half.
// ---------------------------------------------------------------------------
__global__ void k_mod(const float* __restrict__ wr, const float* __restrict__ mw,
                      const float* __restrict__ mb) {
    __shared__ float sT[8*18*35];
    __shared__ float sWp[8*9*20];
    int tid = threadIdx.x;
    int obase = blockIdx.y * 18;
    int b = blockIdx.z;
    int th = (blockIdx.x / 6) * 16, tw = (blockIdx.x % 6) * 32;
    int lyy = tid >> 4, lxx = tid & 15;

    float4 acc0[5], acc1[5];
    #pragma unroll
    for (int j = 0; j < 5; j++) { acc0[j] = make_float4(0,0,0,0); acc1[j] = make_float4(0,0,0,0); }

    for (int chunk = 0; chunk < 8; chunk++) {
        const float* base = wr + (size_t)(b*Cn + chunk*8)*HWn;
        __syncthreads();
        for (int i = tid; i < 1440; i += 256) {
            int c = i / 180; int r = i % 180; int widx = r / 20; int o = r % 20;
            float v = 0.f;
            if (o < 18) v = mw[(size_t)((obase + o)*Cn + chunk*8 + c)*9 + widx];
            sWp[i] = v;
        }
        for (int i = tid; i < 8*18*35; i += 256) {
            int c = i / 630; int r2 = i % 630; int rr = r2 / 35; int cc = r2 % 35;
            int y = th + rr - 1, x = tw + cc - 1;
            float v = 0.f;
            if (cc < 34 && (unsigned)y < (unsigned)Hn && (unsigned)x < (unsigned)Wn)
                v = base[c*HWn + y*Wn + x];
            sT[i] = v;
        }
        __syncthreads();
        for (int c = 0; c < 8; c++) {
            #pragma unroll
            for (int kh = 0; kh < 3; kh++) {
                const float* rowp = sT + c*630 + (lyy+kh)*35 + 2*lxx;
                float xv[4];
                xv[0] = rowp[0]; xv[1] = rowp[1]; xv[2] = rowp[2]; xv[3] = rowp[3];
                #pragma unroll
                for (int kw = 0; kw < 3; kw++) {
                    const float4* wp = (const float4*)(sWp + (c*9 + kh*3 + kw)*20);
                    float a0 = xv[kw], a1 = xv[kw+1];
                    #pragma unroll
                    for (int j = 0; j < 5; j++) {
                        float4 wv = wp[j];
                        acc0[j].x = fmaf(a0, wv.x, acc0[j].x); acc1[j].x = fmaf(a1, wv.x, acc1[j].x);
                        acc0[j].y = fmaf(a0, wv.y, acc0[j].y); acc1[j].y = fmaf(a1, wv.y, acc1[j].y);
                        acc0[j].z = fmaf(a0, wv.z, acc0[j].z); acc1[j].z = fmaf(a1, wv.z, acc1[j].z);
                        acc0[j].w = fmaf(a0, wv.w, acc0[j].w); acc1[j].w = fmaf(a1, wv.w, acc1[j].w);
                    }
                }
            }
        }
    }
    int h = th + lyy, w = tw + 2*lxx;
    const float* a0 = (const float*)acc0;
    const float* a1 = (const float*)acc1;
    #pragma unroll
    for (int o = 0; o < 18; o++) {
        float bo = mb[obase + o];
        float2 r;
        r.x = 1.f + tanhf(0.5f * (a0[o] + bo));
        r.y = 1.f + tanhf(0.5f * (a1[o] + bo));
        *(float2*)(g_mod + (size_t)(b*36 + obase + o)*HWn + h*Wn + w) = r;
    }
}

// ---------------------------------------------------------------------------
// Deformable conv: each thread -> 2 adjacent pixels x 32 output channels
// (blockIdx.y = co-half). Each weight LDS.128 feeds 8 FFMA.
// ---------------------------------------------------------------------------
__device__ __forceinline__ void gather_px(const float* __restrict__ xb, int h, int w,
                                          float oy, float ox, float m, int ki, int kj,
                                          float4 v[4]) {
    float yf = oy + (float)(ki + h - 1);
    float xf = ox + (float)(kj + w - 1);
    float y0f = floorf(yf), x0f = floorf(xf);
    int   y0  = (int)y0f,   x0  = (int)x0f;
    float ly = yf - y0f, lx = xf - x0f;
    float cw[4];
    cw[0] = (1.f-ly)*(1.f-lx)*m;
    cw[1] = (1.f-ly)*lx*m;
    cw[2] = ly*(1.f-lx)*m;
    cw[3] = ly*lx*m;
    #pragma unroll
    for (int j = 0; j < 4; j++) v[j] = make_float4(0,0,0,0);
    #pragma unroll
    for (int corner = 0; corner < 4; corner++) {
        int yi = y0 + (corner >> 1);
        int xi = x0 + (corner & 1);
        float wc = cw[corner];
        if ((unsigned)yi < (unsigned)Hn && (unsigned)xi < (unsigned)Wn) {
            const float4* pp = (const float4*)(xb + (size_t)(yi*Wn + xi)*Cn);
            #pragma unroll
            for (int j = 0; j < 4; j++) {
                float4 xv = pp[j];
                v[j].x = fmaf(wc, xv.x, v[j].x);
                v[j].y = fmaf(wc, xv.y, v[j].y);
                v[j].z = fmaf(wc, xv.z, v[j].z);
                v[j].w = fmaf(wc, xv.w, v[j].w);
            }
        }
    }
}

__global__ void __launch_bounds__(128, 4)
k_deform(const float* __restrict__ rw, const float* __restrict__ offmap,
         float* __restrict__ out) {
    __shared__ float sW[Kn*CGn*32];  // [k][c][co32] = 4608 floats (18KB)
    int tid = threadIdx.x;
    int coHalf = blockIdx.y;
    int p0 = (blockIdx.x*128 + tid)*2;
    int b  = p0 / HWn;
    int hw = p0 - b*HWn;
    int h  = hw / Wn, w = hw - h*Wn;

    float4 acc0[8], acc1[8];
    #pragma unroll
    for (int j = 0; j < 8; j++) { acc0[j] = make_float4(0,0,0,0); acc1[j] = make_float4(0,0,0,0); }

    for (int g = 0; g < Gn; g++) {
        __syncthreads();
        for (int i = tid; i < Kn*CGn*32; i += 128) {
            int k = i >> 9; int c = (i >> 5) & 15; int co = i & 31;
            sW[i] = rw[(size_t)((coHalf*32 + co)*Cn + g*CGn + c)*Kn + k];
        }
        __syncthreads();

        const float* offb = offmap + (size_t)(b*72 + g*18)*HWn + hw;
        const float* modb = g_mod  + (size_t)(b*36 + g*9 )*HWn + hw;
        const float* xb   = g_xnhwc + (size_t)b*HWn*Cn + g*CGn;

        #pragma unroll 1
        for (int k = 0; k < 9; k++) {
            int ki = k/3, kj = k%3;
            float oy0 = offb[(2*k  )*HWn],   oy1 = offb[(2*k  )*HWn + 1];
            float ox0 = offb[(2*k+1)*HWn],   ox1 = offb[(2*k+1)*HWn + 1];
            float m0  = modb[k*HWn],         m1  = modb[k*HWn + 1];

            float4 v0[4], v1[4];
            gather_px(xb, h, w,   oy0, ox0, m0, ki, kj, v0);
            gather_px(xb, h, w+1, oy1, ox1, m1, ki, kj, v1);

            const float* vf0 = (const float*)v0;
            const float* vf1 = (const float*)v1;
            const float* wk = sW + (k << 9);
            #pragma unroll
            for (int c = 0; c < 16; c++) {
                float a = vf0[c], bb = vf1[c];
                const float4* wp = (const float4*)(wk + (c << 5));
                #pragma unroll
                for (int j = 0; j < 8; j++) {
                    float4 wv = wp[j];
                    acc0[j].x = fmaf(a, wv.x, acc0[j].x); acc1[j].x = fmaf(bb, wv.x, acc1[j].x);
                    acc0[j].y = fmaf(a, wv.y, acc0[j].y); acc1[j].y = fmaf(bb, wv.y, acc1[j].y);
                    acc0[j].z = fmaf(a, wv.z, acc0[j].z); acc1[j].z = fmaf(bb, wv.z, acc1[j].z);
                    acc0[j].w = fmaf(a, wv.w, acc0[j].w); acc1[j].w = fmaf(bb, wv.w, acc1[j].w);
                }
            }
        }
    }

    float* obp = out + (size_t)(b*Cn + coHalf*32)*HWn + hw;
    const float* a0 = (const float*)acc0;
    const float* a1 = (const float*)acc1;
    #pragma unroll
    for (int j = 0; j < 32; j++) {
        float2 r; r.x = a0[j]; r.y = a1[j];
        *(float2*)(obp + (size_t)j*HWn) = r;
    }
}

// ---------------------------------------------------------------------------
extern "C" void kernel_launch(void* const* d_in, const int* in_sizes, int n_in,
                              void* d_out, int out_size) {
    const float* wr  = (const float*)d_in[0];
    const float* src = (const float*)d_in[1];
    const float* ow  = (const float*)d_in[2];
    const float* obv = (const float*)d_in[3];
    const float* mw  = (const float*)d_in[4];
    const float* mbv = (const float*)d_in[5];
    const float* rw  = (const float*)d_in[6];

    float* out    = (float*)d_out;
    float* offout = out + (size_t)Bn*Cn*HWn;

    k_transpose<<<dim3(HWn/32, 2, Bn), dim3(32, 8)>>>(wr);
    k_offset  <<<dim3(72, Gn, Bn), 256>>>(wr, src, ow, obv, offout);
    k_mod     <<<dim3(72, 2, Bn), 256>>>(wr, mw, mbv);
    k_deform  <<<dim3(Bn*HWn/256, 2), 128>>>(rw, offout, out);
}